// round 1
// baseline (speedup 1.0000x reference)
#include <cuda_runtime.h>
#include <math.h>

// Problem constants
#define B_    16
#define T_    1000
#define INDIM 257
#define FEAT  771
#define H_    512
#define H3    1536
#define KN    9
#define KS    6
#define M_    (B_*T_)        // 16000
#define FOUT  (H_*KN)        // 4608
#define LDW   260            // padded cols for packed W_out slice (multiple of 4)

// ---------------- scratch (device globals; no runtime allocation) ------------
__device__ float g_X0[T_*B_*H_];        // (T,B,H) after input layer
__device__ float g_U [T_*B_*H3];        // (T,B,3H) SRU pre-activations
__device__ float g_X1[T_*B_*H_];        // SRU layer-1 output
__device__ float g_X2[T_*B_*H_];        // SRU layer-2 output
__device__ float g_conv[B_*KN*T_*H_];   // conv+tanh output (B,KN,T,H)
__device__ float g_hmax[B_*KN*T_*H_];   // pool pass-A (h-direction max)
__device__ float g_Y [M_*FOUT];         // pooled, transposed to (B*T, H*KN)
__device__ float g_Wp[FOUT*LDW];        // packed W_out[:, 257:514], zero-padded

__device__ __forceinline__ float sigf(float x) { return 1.f / (1.f + __expf(-x)); }

// ---------------- generic 128x128x8 SGEMM, 256 threads, 8x8 microtile --------
// A: MxK row-major (lda=K), B: KxN row-major (ldb), M assumed % 128 == 0.
// MODE 0: C[r*N + c] = acc                       (plain, N % 128 == 0)
// MODE 1: C[((r%T)*B + r/T)*H + c] = tanh(acc + bias[c])   (time-major store)
// MODE 2: C[r*INDIM + c] = sigmoid(acc+bias[c]) * gate[r*FEAT + INDIM + c], c<N
template <int MODE>
__global__ __launch_bounds__(256) void sgemm_k(
    const float* __restrict__ A, const float* __restrict__ Bm,
    float* __restrict__ C, int N, int K, int ldb, int Nld,
    const float* __restrict__ bias, const float* __restrict__ gate)
{
    __shared__ float As[8][132];   // padded: conflict-free STS
    __shared__ float Bs[8][128];

    const int tid     = threadIdx.x;
    const int rowBase = blockIdx.y * 128;
    const int colBase = blockIdx.x * 128;

    const int aRow = tid >> 1;          // 0..127
    const int aCol = (tid & 1) * 4;     // 0 or 4
    const int bRow = tid >> 5;          // 0..7
    const int bCol = (tid & 31) * 4;    // 0..124

    const int tRow = (tid >> 4) * 8;
    const int tCol = (tid & 15) * 8;

    float acc[8][8];
    #pragma unroll
    for (int i = 0; i < 8; ++i)
        #pragma unroll
        for (int j = 0; j < 8; ++j) acc[i][j] = 0.f;

    const float* Aptr = A + (size_t)(rowBase + aRow) * K;

    for (int k0 = 0; k0 < K; k0 += 8) {
        // ---- stage global -> regs
        float a0 = 0.f, a1 = 0.f, a2 = 0.f, a3 = 0.f;
        {
            int gk = k0 + aCol;
            if (gk + 3 < K) {                 // fast path (covers K%8==0 fully)
                a0 = Aptr[gk]; a1 = Aptr[gk+1]; a2 = Aptr[gk+2]; a3 = Aptr[gk+3];
            } else {
                if (gk     < K) a0 = Aptr[gk];
                if (gk + 1 < K) a1 = Aptr[gk+1];
                if (gk + 2 < K) a2 = Aptr[gk+2];
                if (gk + 3 < K) a3 = Aptr[gk+3];
            }
        }
        float4 bv = make_float4(0.f, 0.f, 0.f, 0.f);
        {
            int gkb = k0 + bRow;
            int gc  = colBase + bCol;
            if (gkb < K && gc < Nld)
                bv = *(const float4*)(Bm + (size_t)gkb * ldb + gc);
        }
        __syncthreads();                  // previous tile fully consumed
        As[aCol+0][aRow] = a0;
        As[aCol+1][aRow] = a1;
        As[aCol+2][aRow] = a2;
        As[aCol+3][aRow] = a3;
        *(float4*)&Bs[bRow][bCol] = bv;
        __syncthreads();

        // ---- compute
        #pragma unroll
        for (int kk = 0; kk < 8; ++kk) {
            float4 arl = *(const float4*)&As[kk][tRow];
            float4 arh = *(const float4*)&As[kk][tRow + 4];
            float4 brl = *(const float4*)&Bs[kk][tCol];
            float4 brh = *(const float4*)&Bs[kk][tCol + 4];
            float ar[8] = {arl.x, arl.y, arl.z, arl.w, arh.x, arh.y, arh.z, arh.w};
            float br[8] = {brl.x, brl.y, brl.z, brl.w, brh.x, brh.y, brh.z, brh.w};
            #pragma unroll
            for (int i = 0; i < 8; ++i)
                #pragma unroll
                for (int j = 0; j < 8; ++j)
                    acc[i][j] = fmaf(ar[i], br[j], acc[i][j]);
        }
    }

    // ---- epilogue
    #pragma unroll
    for (int i = 0; i < 8; ++i) {
        int r = rowBase + tRow + i;
        if (MODE == 0) {
            float* Cp = C + (size_t)r * N + colBase + tCol;
            #pragma unroll
            for (int j = 0; j < 8; ++j) Cp[j] = acc[i][j];
        } else if (MODE == 1) {
            int orow = (r % T_) * B_ + (r / T_);       // (b*T+t) -> (t*B+b)
            float* Cp = C + (size_t)orow * H_;
            #pragma unroll
            for (int j = 0; j < 8; ++j) {
                int cidx = colBase + tCol + j;
                Cp[cidx] = tanhf(acc[i][j] + bias[cidx]);
            }
        } else {
            #pragma unroll
            for (int j = 0; j < 8; ++j) {
                int cidx = colBase + tCol + j;
                if (cidx < N) {
                    float s = sigf(acc[i][j] + bias[cidx]);
                    C[(size_t)r * INDIM + cidx] = s * gate[(size_t)r * FEAT + INDIM + cidx];
                }
            }
        }
    }
}

// ---------------- SRU recurrence: one thread per (b,h) chain ------------------
__global__ void sru_scan(const float* __restrict__ U, const float* __restrict__ X,
                         float* __restrict__ Xout,
                         const float* __restrict__ v, const float* __restrict__ bb)
{
    int g = blockIdx.x * blockDim.x + threadIdx.x;   // 0..B*H-1
    int b = g / H_, h = g % H_;
    const float vf = v[h],      vr = v[H_ + h];
    const float bf = bb[h],     br = bb[H_ + h];
    const float* Ub = U + b * H3 + h;
    const float* Xb = X + b * H_ + h;
    float*       Ob = Xout + b * H_ + h;

    float c = 0.f;
    // prefetch t=0
    float xt = Ub[0], fp = Ub[H_], rp = Ub[2 * H_], xin = Xb[0];
    for (int t = 0; t < T_; ++t) {
        float nxt = 0.f, nfp = 0.f, nrp = 0.f, nxin = 0.f;
        if (t + 1 < T_) {
            const float* Un = Ub + (size_t)(t + 1) * B_ * H3;
            nxt  = Un[0]; nfp = Un[H_]; nrp = Un[2 * H_];
            nxin = Xb[(size_t)(t + 1) * B_ * H_];
        }
        float f  = sigf(fp + vf * c + bf);
        float rr = sigf(rp + vr * c + br);
        float cn = f * c + (1.f - f) * xt;
        Ob[(size_t)t * B_ * H_] = rr * cn + (1.f - rr) * xin;
        c = cn;
        xt = nxt; fp = nfp; rp = nrp; xin = nxin;
    }
}

// ---------------- conv 6x6, 9 channels, pad (3,2)/(3,2), + bias + tanh --------
__global__ void conv_tanh(const float* __restrict__ X,   // (T,B,H)
                          const float* __restrict__ Wk,  // (9,1,6,6)
                          const float* __restrict__ cb,  // (9)
                          float* __restrict__ out)       // (B,KN,T,H)
{
    __shared__ float sw[KN * KS * KS];   // 324 floats
    for (int i = threadIdx.x; i < KN * KS * KS; i += blockDim.x) sw[i] = Wk[i];
    __syncthreads();

    int h = blockIdx.x * blockDim.x + threadIdx.x;
    int t = blockIdx.y;
    int b = blockIdx.z;

    float acc[KN];
    #pragma unroll
    for (int o = 0; o < KN; ++o) acc[o] = 0.f;

    #pragma unroll
    for (int p = 0; p < KS; ++p) {
        int tt = t - 3 + p;
        if (tt < 0 || tt >= T_) continue;
        const float* row = X + (size_t)(tt * B_ + b) * H_;
        float xv[KS];
        #pragma unroll
        for (int q = 0; q < KS; ++q) {
            int hh = h - 3 + q;
            xv[q] = (hh >= 0 && hh < H_) ? row[hh] : 0.f;
        }
        #pragma unroll
        for (int q = 0; q < KS; ++q) {
            float x = xv[q];
            #pragma unroll
            for (int o = 0; o < KN; ++o)
                acc[o] = fmaf(x, sw[o * 36 + p * 6 + q], acc[o]);
        }
    }
    #pragma unroll
    for (int o = 0; o < KN; ++o)
        out[((size_t)(b * KN + o) * T_ + t) * H_ + h] = tanhf(acc[o] + cb[o]);
}

// ---------------- separable 3x3 max pool ------------------------------------
__global__ void pool_h(const float* __restrict__ in, float* __restrict__ out)
{
    size_t i = (size_t)blockIdx.x * blockDim.x + threadIdx.x;
    if (i >= (size_t)B_ * KN * T_ * H_) return;
    int h = (int)(i % H_);
    float m = in[i];
    if (h > 0)       m = fmaxf(m, in[i - 1]);
    if (h < H_ - 1)  m = fmaxf(m, in[i + 1]);
    out[i] = m;
}

// t-direction max + transpose into (B*T, H*KN) with feature = h*KN + o
__global__ void pool_t(const float* __restrict__ in, float* __restrict__ Y)
{
    int h  = blockIdx.x * blockDim.x + threadIdx.x;
    int t  = blockIdx.y;
    int bk = blockIdx.z;
    int b  = bk / KN, o = bk % KN;
    size_t base = ((size_t)bk * T_ + t) * H_ + h;
    float m = in[base];
    if (t > 0)      m = fmaxf(m, in[base - H_]);
    if (t < T_ - 1) m = fmaxf(m, in[base + H_]);
    Y[((size_t)(b * T_ + t)) * FOUT + h * KN + o] = m;
}

// ---------------- pack W_out[:, 257:514] into (4608 x 260) -------------------
__global__ void pack_w(const float* __restrict__ Wout, float* __restrict__ Wp)
{
    int i = blockIdx.x * blockDim.x + threadIdx.x;
    if (i >= FOUT * LDW) return;
    int k = i / LDW, j = i % LDW;
    Wp[i] = (j < INDIM) ? Wout[(size_t)k * FEAT + INDIM + j] : 0.f;
}

// ---------------- launch ------------------------------------------------------
extern "C" void kernel_launch(void* const* d_in, const int* in_sizes, int n_in,
                              void* d_out, int out_size)
{
    const float* inputs = (const float*)d_in[0];   // (B,T,771)
    const float* W_in   = (const float*)d_in[1];   // (771,512)
    const float* b_in   = (const float*)d_in[2];   // (512)
    const float* W_rnn  = (const float*)d_in[3];   // (2,512,1536)
    const float* v_rnn  = (const float*)d_in[4];   // (2,1024)
    const float* b_rnn  = (const float*)d_in[5];   // (2,1024)
    const float* conv_k = (const float*)d_in[6];   // (9,1,6,6)
    const float* conv_b = (const float*)d_in[7];   // (9)
    const float* W_out  = (const float*)d_in[8];   // (4608,771)
    const float* b_out  = (const float*)d_in[9];   // (771)
    float* out = (float*)d_out;                    // (B,T,257)

    float *X0, *U, *X1, *X2, *CV, *HM, *Y, *Wp;
    cudaGetSymbolAddress((void**)&X0, g_X0);
    cudaGetSymbolAddress((void**)&U,  g_U);
    cudaGetSymbolAddress((void**)&X1, g_X1);
    cudaGetSymbolAddress((void**)&X2, g_X2);
    cudaGetSymbolAddress((void**)&CV, g_conv);
    cudaGetSymbolAddress((void**)&HM, g_hmax);
    cudaGetSymbolAddress((void**)&Y,  g_Y);
    cudaGetSymbolAddress((void**)&Wp, g_Wp);

    // pack output weight slice (only 257 of 771 columns are ever used)
    pack_w<<<(FOUT * LDW + 255) / 256, 256>>>(W_out, Wp);

    // input layer: tanh(inputs @ W_in + b_in), stored time-major (T,B,H)
    sgemm_k<1><<<dim3(H_ / 128, M_ / 128), 256>>>(
        inputs, W_in, X0, H_, FEAT, H_, H_, b_in, nullptr);

    // SRU layer 0
    sgemm_k<0><<<dim3(H3 / 128, M_ / 128), 256>>>(
        X0, W_rnn, U, H3, H_, H3, H3, nullptr, nullptr);
    sru_scan<<<(B_ * H_) / 256, 256>>>(U, X0, X1, v_rnn, b_rnn);

    // SRU layer 1
    sgemm_k<0><<<dim3(H3 / 128, M_ / 128), 256>>>(
        X1, W_rnn + H_ * H3, U, H3, H_, H3, H3, nullptr, nullptr);
    sru_scan<<<(B_ * H_) / 256, 256>>>(U, X1, X2, v_rnn + 2 * H_, b_rnn + 2 * H_);

    // conv + bias + tanh
    conv_tanh<<<dim3(H_ / 128, T_, B_), 128>>>(X2, conv_k, conv_b, CV);

    // separable 3x3 max pool, second pass transposes to (B*T, H*KN)
    {
        size_t tot = (size_t)B_ * KN * T_ * H_;
        pool_h<<<(int)((tot + 255) / 256), 256>>>(CV, HM);
        pool_t<<<dim3(H_ / 256, T_, B_ * KN), 256>>>(HM, Y);
    }

    // output GEMM on the 257-column slice + sigmoid gate * inputs
    sgemm_k<2><<<dim3((INDIM + 127) / 128, M_ / 128), 256>>>(
        Y, Wp, out, INDIM, FOUT, LDW, LDW, b_out + INDIM, inputs);
}